// round 4
// baseline (speedup 1.0000x reference)
#include <cuda_runtime.h>
#include <cuda_fp16.h>
#include <cstdint>

// ===================== Problem constants =====================
#define B_DIM 8192
#define P_DIM 24
#define Q_DIM 12
#define E_DIM 256
#define V_DIM 1000
#define LN_EPS 1e-5f

// fp16 transposed W2: [p][f][e]  (K-major B operand), 3.1 MB static scratch
__device__ __half g_W2Th[P_DIM * E_DIM * E_DIM];

// ===================== Kernel 0: transpose + halve W2 =====================
// W2[p][e][f] (f contiguous) -> g_W2Th[p][f][e] (e contiguous)
__global__ void w2t_kernel(const float* __restrict__ W2) {
    __shared__ float tile[32][33];
    int p  = blockIdx.z;
    int e0 = blockIdx.y * 32;
    int f0 = blockIdx.x * 32;
    int tx = threadIdx.x, ty = threadIdx.y;
    #pragma unroll
    for (int i = ty; i < 32; i += 8)
        tile[i][tx] = W2[((size_t)p * 256 + e0 + i) * 256 + f0 + tx];
    __syncthreads();
    #pragma unroll
    for (int i = ty; i < 32; i += 8) {
        float v = tile[tx][i];  // W2[p][e0+tx][f0+i]
        g_W2Th[((size_t)p * 256 + f0 + i) * 256 + e0 + tx] = __float2half_rn(v);
    }
}

// ===================== Kernel 1: fused gelu-GEMM + bias + LayerNorm =====================
// mma.sync m16n8k16 fp16 -> f32. Single-buffered SMEM (A 64KB fragment-packed,
// B 128KB fragment-packed, C 130KB overlaying B).

// SMEM byte offsets
#define SM_X    0        // 128 f
#define SM_W1   512      // 256 f
#define SM_B1   1536     // 256 f
#define SM_B2   2560     // 256 f
#define SM_G    3584     // 256 f
#define SM_BE   4608     // 256 f
#define SM_PS   5632     // 256 f
#define SM_PQ   6656     // 256 f
#define SM_A    8192     // 65536 B : A fragments [kstep(16)][mtile(8)][lane(32)][reg(4)] b32
#define SM_B    73728    // 131072 B: B fragments [kstep(16)][ntile(32)][lane(32)][reg(2)] b32
                         // C overlay: 128 rows x 260 f32 = 133120 B
#define C_STRIDE 260
#define GEMM_SMEM (73728 + 133120)   // 206848

__device__ __forceinline__ void mma16816(float* c, const uint32_t* a, const uint32_t* b) {
    asm volatile(
        "mma.sync.aligned.m16n8k16.row.col.f32.f16.f16.f32 "
        "{%0,%1,%2,%3}, {%4,%5,%6,%7}, {%8,%9}, {%0,%1,%2,%3};\n"
        : "+f"(c[0]), "+f"(c[1]), "+f"(c[2]), "+f"(c[3])
        : "r"(a[0]), "r"(a[1]), "r"(a[2]), "r"(a[3]), "r"(b[0]), "r"(b[1]));
}

__device__ __forceinline__ float gelu_exact(float t) {
    return 0.5f * t * (1.0f + erff(t * 0.70710678118654752f));
}

__global__ __launch_bounds__(256, 1)
void gemm_ln_kernel(const float* __restrict__ x_num,
                    const float* __restrict__ W1,
                    const float* __restrict__ b1,
                    const float* __restrict__ b2,
                    const float* __restrict__ gamma,
                    const float* __restrict__ beta,
                    float* __restrict__ out) {
    extern __shared__ char smem[];
    const int tid  = threadIdx.x;
    const int lane = tid & 31;
    const int warp = tid >> 5;

    const int p  = blockIdx.x >> 6;      // 0..23
    const int mt = blockIdx.x & 63;      // 0..63
    const int m0 = mt * 128;

    float* xs  = (float*)(smem + SM_X);
    float* w1s = (float*)(smem + SM_W1);
    float* b1s = (float*)(smem + SM_B1);
    float* b2s = (float*)(smem + SM_B2);
    float* gs  = (float*)(smem + SM_G);
    float* bes = (float*)(smem + SM_BE);

    if (tid < 128) xs[tid] = x_num[(size_t)(m0 + tid) * P_DIM + p];
    w1s[tid] = W1[p * 256 + tid];
    b1s[tid] = b1[p * 256 + tid];
    b2s[tid] = b2[p * 256 + tid];
    gs[tid]  = gamma[tid];
    bes[tid] = beta[tid];
    __syncthreads();

    // ---- Prologue A: generate gelu(x*W1+b1) directly in fragment-packed fp16 ----
    // slot (ks, mtile, lane, reg): m = mtile*16 + (lane>>2) + (reg&1)*8
    //                              k = ks*16 + (lane&3)*2 + (reg&2)*4
    {
        uint32_t* abuf = (uint32_t*)(smem + SM_A);
        #pragma unroll
        for (int ksi = 0; ksi < 2; ksi++) {
            const int ks = warp * 2 + ksi;
            #pragma unroll
            for (int mti = 0; mti < 8; mti++) {
                const float xm0 = xs[mti * 16 + (lane >> 2)];
                const float xm1 = xs[mti * 16 + (lane >> 2) + 8];
                #pragma unroll
                for (int reg = 0; reg < 4; reg++) {
                    const float xm = (reg & 1) ? xm1 : xm0;
                    const int k = ks * 16 + (lane & 3) * 2 + (reg & 2) * 4;
                    float h0 = gelu_exact(xm * w1s[k]     + b1s[k]);
                    float h1 = gelu_exact(xm * w1s[k + 1] + b1s[k + 1]);
                    __half2 hv = __floats2half2_rn(h0, h1);
                    abuf[((ks * 8 + mti) * 32 + lane) * 4 + reg] =
                        *reinterpret_cast<uint32_t*>(&hv);
                }
            }
        }
    }

    // ---- Prologue B: stage W2^T (fp16, L2-hot) in fragment-packed layout ----
    // slot (ks, ntile, lane, reg): n = ntile*8 + (lane>>2)
    //                              k-b32 index = ks*8 + (lane&3) + reg*4
    {
        const uint32_t* w2pu = (const uint32_t*)(g_W2Th + (size_t)p * 65536);
        uint32_t* bbuf = (uint32_t*)(smem + SM_B);
        #pragma unroll
        for (int ksi = 0; ksi < 2; ksi++) {
            const int ks = warp * 2 + ksi;
            #pragma unroll
            for (int nt = 0; nt < 32; nt++) {
                const int n = nt * 8 + (lane >> 2);
                #pragma unroll
                for (int reg = 0; reg < 2; reg++) {
                    const int kh = ks * 8 + (lane & 3) + reg * 4;
                    bbuf[((ks * 32 + nt) * 32 + lane) * 2 + reg] = w2pu[n * 128 + kh];
                }
            }
        }
    }
    __syncthreads();

    // ---- Mainloop: warp tile 64x64, 2x4 warp grid ----
    const int wm = warp & 1;   // m half
    const int wn = warp >> 1;  // n quarter
    float acc[4][8][4];
    #pragma unroll
    for (int i = 0; i < 4; i++)
        #pragma unroll
        for (int j = 0; j < 8; j++)
            #pragma unroll
            for (int r = 0; r < 4; r++) acc[i][j][r] = 0.f;

    const uint4* afrag = (const uint4*)(smem + SM_A);
    const uint2* bfrag = (const uint2*)(smem + SM_B);

    #pragma unroll 4
    for (int ks = 0; ks < 16; ks++) {
        uint32_t a[4][4];
        #pragma unroll
        for (int mti = 0; mti < 4; mti++) {
            uint4 v = afrag[(ks * 8 + wm * 4 + mti) * 32 + lane];
            a[mti][0] = v.x; a[mti][1] = v.y; a[mti][2] = v.z; a[mti][3] = v.w;
        }
        #pragma unroll
        for (int nt = 0; nt < 8; nt++) {
            uint2 bv = bfrag[(ks * 32 + wn * 8 + nt) * 32 + lane];
            uint32_t b[2] = {bv.x, bv.y};
            #pragma unroll
            for (int mti = 0; mti < 4; mti++)
                mma16816(acc[mti][nt], a[mti], b);
        }
    }
    __syncthreads();

    // ---- Epilogue 1: acc (+b2) -> SMEM C [128][260] ----
    float* Cs = (float*)(smem + SM_B);
    #pragma unroll
    for (int mti = 0; mti < 4; mti++) {
        const int row = wm * 64 + mti * 16 + (lane >> 2);
        #pragma unroll
        for (int nt = 0; nt < 8; nt++) {
            const int col = wn * 64 + nt * 8 + (lane & 3) * 2;
            const float bb0 = b2s[col], bb1 = b2s[col + 1];
            *(float2*)&Cs[row * C_STRIDE + col] =
                make_float2(acc[mti][nt][0] + bb0, acc[mti][nt][1] + bb1);
            *(float2*)&Cs[(row + 8) * C_STRIDE + col] =
                make_float2(acc[mti][nt][2] + bb0, acc[mti][nt][3] + bb1);
        }
    }
    __syncthreads();

    // ---- Epilogue 2: LayerNorm over 256 cols, store ----
    // thread = (row m, half ch): m = (warp&3)*32+lane, ch = warp>>2
    const int m  = (warp & 3) * 32 + lane;
    const int c0 = (warp >> 2) * 128;

    float v[128];
    float sum = 0.f, sq = 0.f;
    #pragma unroll
    for (int j = 0; j < 128; j += 4) {
        float4 t = *(const float4*)&Cs[m * C_STRIDE + c0 + j];
        v[j] = t.x; v[j + 1] = t.y; v[j + 2] = t.z; v[j + 3] = t.w;
        sum += t.x + t.y + t.z + t.w;
        sq  += t.x * t.x + t.y * t.y + t.z * t.z + t.w * t.w;
    }

    float* ps = (float*)(smem + SM_PS);
    float* pq = (float*)(smem + SM_PQ);
    ps[tid] = sum;
    pq[tid] = sq;
    __syncthreads();
    sum += ps[tid ^ 128];
    sq  += pq[tid ^ 128];

    const float mu   = sum * (1.0f / 256.0f);
    const float var  = sq * (1.0f / 256.0f) - mu * mu;
    const float rstd = rsqrtf(var + LN_EPS);

    float4* o4 = (float4*)(out + (((size_t)(m0 + m) * 36 + p) * 256 + c0));
    #pragma unroll
    for (int j = 0; j < 128; j += 4) {
        float4 r;
        r.x = (v[j + 0] - mu) * rstd * gs[c0 + j + 0] + bes[c0 + j + 0];
        r.y = (v[j + 1] - mu) * rstd * gs[c0 + j + 1] + bes[c0 + j + 1];
        r.z = (v[j + 2] - mu) * rstd * gs[c0 + j + 2] + bes[c0 + j + 2];
        r.w = (v[j + 3] - mu) * rstd * gs[c0 + j + 3] + bes[c0 + j + 3];
        o4[j >> 2] = r;
    }
}

// ===================== Kernel 2: embedding gather + LayerNorm =====================
// x_cat is int32 (JAX default x64-disabled downcasts int64 -> int32).
__global__ __launch_bounds__(256)
void cat_ln_kernel(const int* __restrict__ x_cat,
                   const float* __restrict__ emb,
                   const float* __restrict__ gamma,
                   const float* __restrict__ beta,
                   float* __restrict__ out) {
    const int gwarp = (blockIdx.x * blockDim.x + threadIdx.x) >> 5;
    const int lid = threadIdx.x & 31;
    if (gwarp >= B_DIM * Q_DIM) return;
    const int b = gwarp / Q_DIM;
    const int q = gwarp % Q_DIM;

    const int idx = x_cat[(size_t)b * Q_DIM + q];
    const float4* src = (const float4*)(emb + ((size_t)q * V_DIM + (size_t)idx) * E_DIM);
    float4 v0 = src[lid];
    float4 v1 = src[lid + 32];

    float sum = v0.x + v0.y + v0.z + v0.w + v1.x + v1.y + v1.z + v1.w;
    float sq  = v0.x * v0.x + v0.y * v0.y + v0.z * v0.z + v0.w * v0.w
              + v1.x * v1.x + v1.y * v1.y + v1.z * v1.z + v1.w * v1.w;
    #pragma unroll
    for (int off = 16; off > 0; off >>= 1) {
        sum += __shfl_xor_sync(0xFFFFFFFFu, sum, off);
        sq  += __shfl_xor_sync(0xFFFFFFFFu, sq, off);
    }
    const float mu   = sum * (1.0f / 256.0f);
    const float var  = sq * (1.0f / 256.0f) - mu * mu;
    const float rstd = rsqrtf(var + LN_EPS);

    const float4* g4  = (const float4*)gamma;
    const float4* be4 = (const float4*)beta;
    float4 g0 = g4[lid], g1 = g4[lid + 32];
    float4 e0 = be4[lid], e1 = be4[lid + 32];

    float4 r0, r1;
    r0.x = (v0.x - mu) * rstd * g0.x + e0.x;
    r0.y = (v0.y - mu) * rstd * g0.y + e0.y;
    r0.z = (v0.z - mu) * rstd * g0.z + e0.z;
    r0.w = (v0.w - mu) * rstd * g0.w + e0.w;
    r1.x = (v1.x - mu) * rstd * g1.x + e1.x;
    r1.y = (v1.y - mu) * rstd * g1.y + e1.y;
    r1.z = (v1.z - mu) * rstd * g1.z + e1.z;
    r1.w = (v1.w - mu) * rstd * g1.w + e1.w;

    float4* dst = (float4*)(out + ((size_t)b * 36 + 24 + q) * E_DIM);
    dst[lid] = r0;
    dst[lid + 32] = r1;
}

// ===================== Launch =====================
extern "C" void kernel_launch(void* const* d_in, const int* in_sizes, int n_in,
                              void* d_out, int out_size) {
    const float* x_num = (const float*)d_in[0];
    const int*   x_cat = (const int*)d_in[1];
    const float* W1    = (const float*)d_in[2];
    const float* b1    = (const float*)d_in[3];
    const float* W2    = (const float*)d_in[4];
    const float* b2    = (const float*)d_in[5];
    const float* emb   = (const float*)d_in[6];
    const float* gamma = (const float*)d_in[7];
    const float* beta  = (const float*)d_in[8];
    float* out = (float*)d_out;

    cudaFuncSetAttribute(gemm_ln_kernel,
                         cudaFuncAttributeMaxDynamicSharedMemorySize, GEMM_SMEM);

    w2t_kernel<<<dim3(8, 8, 24), dim3(32, 8)>>>(W2);
    gemm_ln_kernel<<<P_DIM * (B_DIM / 128), 256, GEMM_SMEM>>>(
        x_num, W1, b1, b2, gamma, beta, out);
    cat_ln_kernel<<<(B_DIM * Q_DIM) / 8, 256>>>(x_cat, emb, gamma, beta, out);
}

// round 5
// speedup vs baseline: 1.4097x; 1.4097x over previous
#include <cuda_runtime.h>
#include <cuda_fp16.h>
#include <cstdint>

// ===================== Problem constants =====================
#define B_DIM 8192
#define P_DIM 24
#define Q_DIM 12
#define E_DIM 256
#define V_DIM 1000
#define LN_EPS 1e-5f

#define GEMM_CTAS 384          // 24 p * 16 m-slots
#define TILES_PER_CTA 4        // 64 m-tiles / 16 slots
#define CAT_CTAS 384
#define TOK_PER_CAT_CTA 256    // 98304 / 384

// fp16 transposed W2: [p][f][e]  (K-major B operand), 3.1 MB static scratch
__device__ __half g_W2Th[P_DIM * E_DIM * E_DIM];

// ===================== Kernel 0: transpose + halve W2 =====================
__global__ void w2t_kernel(const float* __restrict__ W2) {
    __shared__ float tile[32][33];
    int p  = blockIdx.z;
    int e0 = blockIdx.y * 32;
    int f0 = blockIdx.x * 32;
    int tx = threadIdx.x, ty = threadIdx.y;
    #pragma unroll
    for (int i = ty; i < 32; i += 8)
        tile[i][tx] = W2[((size_t)p * 256 + e0 + i) * 256 + f0 + tx];
    __syncthreads();
    #pragma unroll
    for (int i = ty; i < 32; i += 8) {
        float v = tile[tx][i];
        g_W2Th[((size_t)p * 256 + f0 + i) * 256 + e0 + tx] = __float2half_rn(v);
    }
}

// ===================== Fused kernel =====================
// blocks [0,384): persistent gemm+LN, 4 m-tiles each, B frags staged once.
// blocks [384,768): embedding gather + LN (no smem use).

// SMEM byte offsets (gemm path)
#define SM_X    0        // 128 f
#define SM_W1   512      // 256 f
#define SM_B1   1536     // 256 f
#define SM_B2   2560     // 256 f
#define SM_G    3584     // 256 f
#define SM_BE   4608     // 256 f
#define SM_STAT 5632     // 128 rows x 4 warps x float2 = 4096 B
#define SM_A    16384    // 65536 B : A frags [ks(16)][mtile(8)][lane(32)][4] b32
#define SM_B    81920    // 131072 B: B frags [ks(16)][ntp(16)][lane(32)][4] b32
#define GEMM_SMEM (81920 + 131072)   // 212992

__device__ __forceinline__ void mma16816(float* c, const uint32_t* a, const uint32_t* b) {
    asm volatile(
        "mma.sync.aligned.m16n8k16.row.col.f32.f16.f16.f32 "
        "{%0,%1,%2,%3}, {%4,%5,%6,%7}, {%8,%9}, {%0,%1,%2,%3};\n"
        : "+f"(c[0]), "+f"(c[1]), "+f"(c[2]), "+f"(c[3])
        : "r"(a[0]), "r"(a[1]), "r"(a[2]), "r"(a[3]), "r"(b[0]), "r"(b[1]));
}

__device__ __forceinline__ float gelu_exact(float t) {
    return 0.5f * t * (1.0f + erff(t * 0.70710678118654752f));
}

__global__ __launch_bounds__(256, 1)
void fused_kernel(const float* __restrict__ x_num,
                  const int*   __restrict__ x_cat,
                  const float* __restrict__ W1,
                  const float* __restrict__ b1,
                  const float* __restrict__ b2,
                  const float* __restrict__ emb,
                  const float* __restrict__ gamma,
                  const float* __restrict__ beta,
                  float* __restrict__ out) {
    const int tid  = threadIdx.x;
    const int lane = tid & 31;
    const int warp = tid >> 5;

    // ================= CAT PATH =================
    if (blockIdx.x >= GEMM_CTAS) {
        const int blk2 = blockIdx.x - GEMM_CTAS;
        const float4* g4  = (const float4*)gamma;
        const float4* be4 = (const float4*)beta;
        float4 g0 = g4[lane], g1 = g4[lane + 32];
        float4 e0 = be4[lane], e1 = be4[lane + 32];

        #pragma unroll 1
        for (int it = 0; it < TOK_PER_CAT_CTA / 8; it++) {
            const int tok = blk2 * TOK_PER_CAT_CTA + it * 8 + warp;
            const int b = tok / Q_DIM;
            const int q = tok % Q_DIM;
            const int idx = x_cat[(size_t)b * Q_DIM + q];
            const float4* src = (const float4*)(emb + ((size_t)q * V_DIM + idx) * E_DIM);
            float4 v0 = src[lane];
            float4 v1 = src[lane + 32];

            float sum = v0.x + v0.y + v0.z + v0.w + v1.x + v1.y + v1.z + v1.w;
            float sq  = v0.x * v0.x + v0.y * v0.y + v0.z * v0.z + v0.w * v0.w
                      + v1.x * v1.x + v1.y * v1.y + v1.z * v1.z + v1.w * v1.w;
            #pragma unroll
            for (int off = 16; off > 0; off >>= 1) {
                sum += __shfl_xor_sync(0xFFFFFFFFu, sum, off);
                sq  += __shfl_xor_sync(0xFFFFFFFFu, sq, off);
            }
            const float mu   = sum * (1.0f / 256.0f);
            const float var  = sq * (1.0f / 256.0f) - mu * mu;
            const float rstd = rsqrtf(var + LN_EPS);

            float4 r0, r1;
            r0.x = (v0.x - mu) * rstd * g0.x + e0.x;
            r0.y = (v0.y - mu) * rstd * g0.y + e0.y;
            r0.z = (v0.z - mu) * rstd * g0.z + e0.z;
            r0.w = (v0.w - mu) * rstd * g0.w + e0.w;
            r1.x = (v1.x - mu) * rstd * g1.x + e1.x;
            r1.y = (v1.y - mu) * rstd * g1.y + e1.y;
            r1.z = (v1.z - mu) * rstd * g1.z + e1.z;
            r1.w = (v1.w - mu) * rstd * g1.w + e1.w;

            float4* dst = (float4*)(out + ((size_t)b * 36 + 24 + q) * E_DIM);
            dst[lane] = r0;
            dst[lane + 32] = r1;
        }
        return;
    }

    // ================= GEMM PATH =================
    extern __shared__ char smem[];
    const int p     = blockIdx.x >> 4;   // 0..23
    const int mslot = blockIdx.x & 15;   // 0..15

    float* xs  = (float*)(smem + SM_X);
    float* w1s = (float*)(smem + SM_W1);
    float* b1s = (float*)(smem + SM_B1);
    float* b2s = (float*)(smem + SM_B2);
    float* gs  = (float*)(smem + SM_G);
    float* bes = (float*)(smem + SM_BE);
    float* statb = (float*)(smem + SM_STAT);   // [128][8] floats

    w1s[tid] = W1[p * 256 + tid];
    b1s[tid] = b1[p * 256 + tid];
    b2s[tid] = b2[p * 256 + tid];
    gs[tid]  = gamma[tid];
    bes[tid] = beta[tid];

    // ---- Stage B frags ONCE: [ks][ntp(16)][lane][4] uint32 (uint4 slots) ----
    // frag (ks, nt, lane, reg): n = nt*8 + (lane>>2), k-b32 = ks*8 + (lane&3) + reg*4
    // slot packs nt=2ntp (x,y) and nt=2ntp+1 (z,w)
    {
        const uint32_t* w2pu = (const uint32_t*)(g_W2Th + (size_t)p * 65536);
        uint4* bbuf4 = (uint4*)(smem + SM_B);
        const int ne_base = (lane >> 2);
        const int kh_base = (lane & 3);
        #pragma unroll
        for (int ksi = 0; ksi < 2; ksi++) {
            const int ks = warp * 2 + ksi;
            #pragma unroll
            for (int ntp = 0; ntp < 16; ntp++) {
                const int n_e = (2 * ntp) * 8 + ne_base;
                const int n_o = n_e + 8;
                const int kh0 = ks * 8 + kh_base;
                const int kh1 = kh0 + 4;
                uint4 v;
                v.x = w2pu[n_e * 128 + kh0];
                v.y = w2pu[n_e * 128 + kh1];
                v.z = w2pu[n_o * 128 + kh0];
                v.w = w2pu[n_o * 128 + kh1];
                bbuf4[(ks * 16 + ntp) * 32 + lane] = v;
            }
        }
    }
    __syncthreads();

    const int wm = warp & 1;   // m half
    const int wn = warp >> 1;  // n quarter (0..3)

    // per-thread LN column constants (16 cols: 8 ntl x 2)
    float2 b2v[8], gv[8], bv[8];
    #pragma unroll
    for (int ntl = 0; ntl < 8; ntl++) {
        const int col = wn * 64 + ntl * 8 + (lane & 3) * 2;
        b2v[ntl] = *(float2*)&b2s[col];
        gv[ntl]  = *(float2*)&gs[col];
        bv[ntl]  = *(float2*)&bes[col];
    }

    // ---- Tile loop ----
    for (int t = 0; t < TILES_PER_CTA; t++) {
        const int m0 = (mslot * TILES_PER_CTA + t) * 128;

        if (tid < 128) xs[tid] = x_num[(size_t)(m0 + tid) * P_DIM + p];
        __syncthreads();   // xs ready; prev tile's A reads & stat reads done

        // ---- Prologue A: gelu(x*W1+b1) -> fragment-packed fp16 ----
        {
            uint32_t* abuf = (uint32_t*)(smem + SM_A);
            #pragma unroll
            for (int ksi = 0; ksi < 2; ksi++) {
                const int ks = warp * 2 + ksi;
                #pragma unroll
                for (int mti = 0; mti < 8; mti++) {
                    const float xm0 = xs[mti * 16 + (lane >> 2)];
                    const float xm1 = xs[mti * 16 + (lane >> 2) + 8];
                    #pragma unroll
                    for (int reg = 0; reg < 4; reg++) {
                        const float xm = (reg & 1) ? xm1 : xm0;
                        const int k = ks * 16 + (lane & 3) * 2 + (reg & 2) * 4;
                        float h0 = gelu_exact(xm * w1s[k]     + b1s[k]);
                        float h1 = gelu_exact(xm * w1s[k + 1] + b1s[k + 1]);
                        __half2 hv = __floats2half2_rn(h0, h1);
                        abuf[((ks * 8 + mti) * 32 + lane) * 4 + reg] =
                            *reinterpret_cast<uint32_t*>(&hv);
                    }
                }
            }
        }
        __syncthreads();

        // ---- Mainloop: warp tile 64x64 ----
        float acc[4][8][4];
        #pragma unroll
        for (int i = 0; i < 4; i++)
            #pragma unroll
            for (int j = 0; j < 8; j++)
                #pragma unroll
                for (int r = 0; r < 4; r++) acc[i][j][r] = 0.f;

        const uint4* afrag = (const uint4*)(smem + SM_A);
        const uint4* bfrag = (const uint4*)(smem + SM_B);

        #pragma unroll
        for (int ks = 0; ks < 16; ks++) {
            uint32_t a[4][4];
            #pragma unroll
            for (int mti = 0; mti < 4; mti++) {
                uint4 v = afrag[(ks * 8 + wm * 4 + mti) * 32 + lane];
                a[mti][0] = v.x; a[mti][1] = v.y; a[mti][2] = v.z; a[mti][3] = v.w;
            }
            #pragma unroll
            for (int ntlp = 0; ntlp < 4; ntlp++) {
                uint4 bv4 = bfrag[(ks * 16 + wn * 4 + ntlp) * 32 + lane];
                uint32_t b0[2] = {bv4.x, bv4.y};
                uint32_t b1r[2] = {bv4.z, bv4.w};
                #pragma unroll
                for (int mti = 0; mti < 4; mti++) {
                    mma16816(acc[mti][ntlp * 2],     a[mti], b0);
                    mma16816(acc[mti][ntlp * 2 + 1], a[mti], b1r);
                }
            }
        }

        // ---- Epilogue: +b2, register LN ----
        #pragma unroll
        for (int mti = 0; mti < 4; mti++)
            #pragma unroll
            for (int ntl = 0; ntl < 8; ntl++) {
                acc[mti][ntl][0] += b2v[ntl].x;
                acc[mti][ntl][1] += b2v[ntl].y;
                acc[mti][ntl][2] += b2v[ntl].x;
                acc[mti][ntl][3] += b2v[ntl].y;
            }

        // row partials (8 rows/thread: 4 mti x 2 half), reduce over lane&3
        float rs[4][2], rq[4][2];
        #pragma unroll
        for (int mti = 0; mti < 4; mti++)
            #pragma unroll
            for (int h = 0; h < 2; h++) {
                float s = 0.f, q = 0.f;
                #pragma unroll
                for (int ntl = 0; ntl < 8; ntl++) {
                    float v0 = acc[mti][ntl][h * 2];
                    float v1 = acc[mti][ntl][h * 2 + 1];
                    s += v0 + v1;
                    q += v0 * v0 + v1 * v1;
                }
                s += __shfl_xor_sync(0xFFFFFFFFu, s, 1);
                q += __shfl_xor_sync(0xFFFFFFFFu, q, 1);
                s += __shfl_xor_sync(0xFFFFFFFFu, s, 2);
                q += __shfl_xor_sync(0xFFFFFFFFu, q, 2);
                rs[mti][h] = s;
                rq[mti][h] = q;
            }

        if ((lane & 3) == 0) {
            #pragma unroll
            for (int mti = 0; mti < 4; mti++)
                #pragma unroll
                for (int h = 0; h < 2; h++) {
                    const int row = wm * 64 + mti * 16 + (lane >> 2) + h * 8;
                    *(float2*)&statb[row * 8 + wn * 2] = make_float2(rs[mti][h], rq[mti][h]);
                }
        }
        __syncthreads();

        #pragma unroll
        for (int mti = 0; mti < 4; mti++)
            #pragma unroll
            for (int h = 0; h < 2; h++) {
                const int row = wm * 64 + mti * 16 + (lane >> 2) + h * 8;
                float4 s01 = *(float4*)&statb[row * 8];
                float4 s23 = *(float4*)&statb[row * 8 + 4];
                float sum = s01.x + s01.z + s23.x + s23.z;
                float sq  = s01.y + s01.w + s23.y + s23.w;
                const float mu   = sum * (1.0f / 256.0f);
                const float var  = sq * (1.0f / 256.0f) - mu * mu;
                const float rstd = rsqrtf(var + LN_EPS);

                float* orow = out + (((size_t)(m0 + row) * 36 + p) * 256);
                #pragma unroll
                for (int ntl = 0; ntl < 8; ntl++) {
                    const int col = wn * 64 + ntl * 8 + (lane & 3) * 2;
                    float2 r;
                    r.x = (acc[mti][ntl][h * 2]     - mu) * rstd * gv[ntl].x + bv[ntl].x;
                    r.y = (acc[mti][ntl][h * 2 + 1] - mu) * rstd * gv[ntl].y + bv[ntl].y;
                    *(float2*)&orow[col] = r;
                }
            }
        __syncthreads();   // protect statb before next tile rewrites it
    }
}

// ===================== Launch =====================
extern "C" void kernel_launch(void* const* d_in, const int* in_sizes, int n_in,
                              void* d_out, int out_size) {
    const float* x_num = (const float*)d_in[0];
    const int*   x_cat = (const int*)d_in[1];
    const float* W1    = (const float*)d_in[2];
    const float* b1    = (const float*)d_in[3];
    const float* W2    = (const float*)d_in[4];
    const float* b2    = (const float*)d_in[5];
    const float* emb   = (const float*)d_in[6];
    const float* gamma = (const float*)d_in[7];
    const float* beta  = (const float*)d_in[8];
    float* out = (float*)d_out;

    cudaFuncSetAttribute(fused_kernel,
                         cudaFuncAttributeMaxDynamicSharedMemorySize, GEMM_SMEM);

    w2t_kernel<<<dim3(8, 8, 24), dim3(32, 8)>>>(W2);
    fused_kernel<<<GEMM_CTAS + CAT_CTAS, 256, GEMM_SMEM>>>(
        x_num, x_cat, W1, b1, b2, emb, gamma, beta, out);
}

// round 6
// speedup vs baseline: 1.4743x; 1.0458x over previous
#include <cuda_runtime.h>
#include <cuda_fp16.h>
#include <cstdint>

// ===================== Problem constants =====================
#define B_DIM 8192
#define P_DIM 24
#define Q_DIM 12
#define E_DIM 256
#define V_DIM 1000
#define LN_EPS 1e-5f

#define GEMM_CTAS 384          // 24 p * 16 m-slots
#define TILES_PER_CTA 4        // 64 m-tiles / 16 slots
#define CAT_CTAS 192
#define TOK_PER_CAT_CTA 512    // 98304 / 192

// fp16 transposed W2: [p][f][e]  (K-major B operand), 3.1 MB static scratch
__device__ __half g_W2Th[P_DIM * E_DIM * E_DIM];

// ===================== Kernel 0: transpose + halve W2 =====================
__global__ void w2t_kernel(const float* __restrict__ W2) {
    __shared__ float tile[32][33];
    int p  = blockIdx.z;
    int e0 = blockIdx.y * 32;
    int f0 = blockIdx.x * 32;
    int tx = threadIdx.x, ty = threadIdx.y;
    #pragma unroll
    for (int i = ty; i < 32; i += 8)
        tile[i][tx] = W2[((size_t)p * 256 + e0 + i) * 256 + f0 + tx];
    __syncthreads();
    #pragma unroll
    for (int i = ty; i < 32; i += 8) {
        float v = tile[tx][i];
        g_W2Th[((size_t)p * 256 + f0 + i) * 256 + e0 + tx] = __float2half_rn(v);
    }
}

// ===================== Fused kernel (512 threads) =====================
// blocks [0,384): persistent gemm+LN, 4 m-tiles each, B frags staged once.
// blocks [384,576): embedding gather + LN.

// SMEM byte offsets (gemm path)
#define SM_X    0        // 128 f
#define SM_W1   512      // 256 f
#define SM_B1   1536     // 256 f
#define SM_B2   2560     // 256 f
#define SM_G    3584     // 256 f
#define SM_BE   4608     // 256 f
#define SM_STAT 5632     // 128 rows x 8 wn x float2 = 8192 B   (ends 13824)
#define SM_A    16384    // 65536 B : A frags [ks(16)][mtile(8)][lane(32)][4] b32
#define SM_B    81920    // 131072 B: B frags [ks(16)][ntp(16)][lane(32)][4] b32
#define GEMM_SMEM (81920 + 131072)   // 212992

__device__ __forceinline__ void mma16816(float* c, const uint32_t* a, const uint32_t* b) {
    asm volatile(
        "mma.sync.aligned.m16n8k16.row.col.f32.f16.f16.f32 "
        "{%0,%1,%2,%3}, {%4,%5,%6,%7}, {%8,%9}, {%0,%1,%2,%3};\n"
        : "+f"(c[0]), "+f"(c[1]), "+f"(c[2]), "+f"(c[3])
        : "r"(a[0]), "r"(a[1]), "r"(a[2]), "r"(a[3]), "r"(b[0]), "r"(b[1]));
}

__device__ __forceinline__ float gelu_exact(float t) {
    return 0.5f * t * (1.0f + erff(t * 0.70710678118654752f));
}

__global__ __launch_bounds__(512, 1)
void fused_kernel(const float* __restrict__ x_num,
                  const int*   __restrict__ x_cat,
                  const float* __restrict__ W1,
                  const float* __restrict__ b1,
                  const float* __restrict__ b2,
                  const float* __restrict__ emb,
                  const float* __restrict__ gamma,
                  const float* __restrict__ beta,
                  float* __restrict__ out) {
    const int tid  = threadIdx.x;
    const int lane = tid & 31;
    const int warp = tid >> 5;       // 0..15

    // ================= CAT PATH =================
    if (blockIdx.x >= GEMM_CTAS) {
        const int blk2 = blockIdx.x - GEMM_CTAS;
        const float4* g4  = (const float4*)gamma;
        const float4* be4 = (const float4*)beta;
        float4 g0 = g4[lane], g1 = g4[lane + 32];
        float4 e0 = be4[lane], e1 = be4[lane + 32];

        #pragma unroll 1
        for (int it = 0; it < TOK_PER_CAT_CTA / 16; it++) {
            const int tok = blk2 * TOK_PER_CAT_CTA + it * 16 + warp;
            const int b = tok / Q_DIM;
            const int q = tok % Q_DIM;
            const int idx = x_cat[(size_t)b * Q_DIM + q];
            const float4* src = (const float4*)(emb + ((size_t)q * V_DIM + idx) * E_DIM);
            float4 v0 = src[lane];
            float4 v1 = src[lane + 32];

            float sum = v0.x + v0.y + v0.z + v0.w + v1.x + v1.y + v1.z + v1.w;
            float sq  = v0.x * v0.x + v0.y * v0.y + v0.z * v0.z + v0.w * v0.w
                      + v1.x * v1.x + v1.y * v1.y + v1.z * v1.z + v1.w * v1.w;
            #pragma unroll
            for (int off = 16; off > 0; off >>= 1) {
                sum += __shfl_xor_sync(0xFFFFFFFFu, sum, off);
                sq  += __shfl_xor_sync(0xFFFFFFFFu, sq, off);
            }
            const float mu   = sum * (1.0f / 256.0f);
            const float var  = sq * (1.0f / 256.0f) - mu * mu;
            const float rstd = rsqrtf(var + LN_EPS);

            float4 r0, r1;
            r0.x = (v0.x - mu) * rstd * g0.x + e0.x;
            r0.y = (v0.y - mu) * rstd * g0.y + e0.y;
            r0.z = (v0.z - mu) * rstd * g0.z + e0.z;
            r0.w = (v0.w - mu) * rstd * g0.w + e0.w;
            r1.x = (v1.x - mu) * rstd * g1.x + e1.x;
            r1.y = (v1.y - mu) * rstd * g1.y + e1.y;
            r1.z = (v1.z - mu) * rstd * g1.z + e1.z;
            r1.w = (v1.w - mu) * rstd * g1.w + e1.w;

            float4* dst = (float4*)(out + ((size_t)b * 36 + 24 + q) * E_DIM);
            dst[lane] = r0;
            dst[lane + 32] = r1;
        }
        return;
    }

    // ================= GEMM PATH =================
    extern __shared__ char smem[];
    const int p     = blockIdx.x >> 4;   // 0..23
    const int mslot = blockIdx.x & 15;   // 0..15

    float* xs  = (float*)(smem + SM_X);
    float* w1s = (float*)(smem + SM_W1);
    float* b1s = (float*)(smem + SM_B1);
    float* b2s = (float*)(smem + SM_B2);
    float* gs  = (float*)(smem + SM_G);
    float* bes = (float*)(smem + SM_BE);
    float* statb = (float*)(smem + SM_STAT);   // [128][16] floats

    if (tid < 256) {
        w1s[tid] = W1[p * 256 + tid];
        b1s[tid] = b1[p * 256 + tid];
        b2s[tid] = b2[p * 256 + tid];
        gs[tid]  = gamma[tid];
        bes[tid] = beta[tid];
    }

    // ---- Stage B frags ONCE: [ks][ntp(16)][lane][4] uint32 (uint4 slots) ----
    // frag (ks, nt, lane, reg): n = nt*8 + (lane>>2), k-b32 = ks*8 + (lane&3) + reg*4
    // slot packs nt=2ntp (x,y) and nt=2ntp+1 (z,w).  Each warp handles ks = warp.
    {
        const uint32_t* w2pu = (const uint32_t*)(g_W2Th + (size_t)p * 65536);
        uint4* bbuf4 = (uint4*)(smem + SM_B);
        const int ks = warp;
        const int ne_base = (lane >> 2);
        const int kh0 = ks * 8 + (lane & 3);
        const int kh1 = kh0 + 4;
        #pragma unroll
        for (int ntp = 0; ntp < 16; ntp++) {
            const int n_e = (2 * ntp) * 8 + ne_base;
            const int n_o = n_e + 8;
            uint4 v;
            v.x = w2pu[n_e * 128 + kh0];
            v.y = w2pu[n_e * 128 + kh1];
            v.z = w2pu[n_o * 128 + kh0];
            v.w = w2pu[n_o * 128 + kh1];
            bbuf4[(ks * 16 + ntp) * 32 + lane] = v;
        }
    }
    __syncthreads();

    const int wm = warp & 1;   // m half (0..1)
    const int wn = warp >> 1;  // n octet (0..7), 32 cols each

    // per-thread b2 constants (8 cols: 4 ntl x 2)
    float2 b2v[4];
    #pragma unroll
    for (int ntl = 0; ntl < 4; ntl++)
        b2v[ntl] = *(float2*)&b2s[wn * 32 + ntl * 8 + (lane & 3) * 2];

    // ---- Tile loop ----
    for (int t = 0; t < TILES_PER_CTA; t++) {
        const int m0 = (mslot * TILES_PER_CTA + t) * 128;

        if (tid < 128) xs[tid] = x_num[(size_t)(m0 + tid) * P_DIM + p];
        __syncthreads();   // xs ready; prev tile's A reads & stat reads done

        // ---- Prologue A: gelu(x*W1+b1) -> fragment-packed fp16 (warp = ks) ----
        {
            uint32_t* abuf = (uint32_t*)(smem + SM_A);
            const int ks = warp;
            #pragma unroll
            for (int mti = 0; mti < 8; mti++) {
                const float xm0 = xs[mti * 16 + (lane >> 2)];
                const float xm1 = xs[mti * 16 + (lane >> 2) + 8];
                #pragma unroll
                for (int reg = 0; reg < 4; reg++) {
                    const float xm = (reg & 1) ? xm1 : xm0;
                    const int k = ks * 16 + (lane & 3) * 2 + (reg & 2) * 4;
                    float h0 = gelu_exact(xm * w1s[k]     + b1s[k]);
                    float h1 = gelu_exact(xm * w1s[k + 1] + b1s[k + 1]);
                    __half2 hv = __floats2half2_rn(h0, h1);
                    abuf[((ks * 8 + mti) * 32 + lane) * 4 + reg] =
                        *reinterpret_cast<uint32_t*>(&hv);
                }
            }
        }
        __syncthreads();

        // ---- Mainloop: warp tile 64x32 ----
        float acc[4][4][4];
        #pragma unroll
        for (int i = 0; i < 4; i++)
            #pragma unroll
            for (int j = 0; j < 4; j++)
                #pragma unroll
                for (int r = 0; r < 4; r++) acc[i][j][r] = 0.f;

        const uint4* afrag = (const uint4*)(smem + SM_A);
        const uint4* bfrag = (const uint4*)(smem + SM_B);

        #pragma unroll
        for (int ks = 0; ks < 16; ks++) {
            uint32_t a[4][4];
            #pragma unroll
            for (int mti = 0; mti < 4; mti++) {
                uint4 v = afrag[(ks * 8 + wm * 4 + mti) * 32 + lane];
                a[mti][0] = v.x; a[mti][1] = v.y; a[mti][2] = v.z; a[mti][3] = v.w;
            }
            #pragma unroll
            for (int i = 0; i < 2; i++) {
                uint4 bv4 = bfrag[(ks * 16 + wn * 2 + i) * 32 + lane];
                uint32_t b0[2] = {bv4.x, bv4.y};
                uint32_t b1r[2] = {bv4.z, bv4.w};
                #pragma unroll
                for (int mti = 0; mti < 4; mti++) {
                    mma16816(acc[mti][i * 2],     a[mti], b0);
                    mma16816(acc[mti][i * 2 + 1], a[mti], b1r);
                }
            }
        }

        // ---- Epilogue: +b2, register LN ----
        #pragma unroll
        for (int mti = 0; mti < 4; mti++)
            #pragma unroll
            for (int ntl = 0; ntl < 4; ntl++) {
                acc[mti][ntl][0] += b2v[ntl].x;
                acc[mti][ntl][1] += b2v[ntl].y;
                acc[mti][ntl][2] += b2v[ntl].x;
                acc[mti][ntl][3] += b2v[ntl].y;
            }

        // row partials (8 rows/thread: 4 mti x 2 half), reduce over lane&3 -> 32-col partials
        #pragma unroll
        for (int mti = 0; mti < 4; mti++)
            #pragma unroll
            for (int h = 0; h < 2; h++) {
                float s = 0.f, q = 0.f;
                #pragma unroll
                for (int ntl = 0; ntl < 4; ntl++) {
                    float v0 = acc[mti][ntl][h * 2];
                    float v1 = acc[mti][ntl][h * 2 + 1];
                    s += v0 + v1;
                    q += v0 * v0 + v1 * v1;
                }
                s += __shfl_xor_sync(0xFFFFFFFFu, s, 1);
                q += __shfl_xor_sync(0xFFFFFFFFu, q, 1);
                s += __shfl_xor_sync(0xFFFFFFFFu, s, 2);
                q += __shfl_xor_sync(0xFFFFFFFFu, q, 2);
                if ((lane & 3) == 0) {
                    const int row = wm * 64 + mti * 16 + (lane >> 2) + h * 8;
                    *(float2*)&statb[row * 16 + wn * 2] = make_float2(s, q);
                }
            }
        __syncthreads();

        #pragma unroll
        for (int mti = 0; mti < 4; mti++)
            #pragma unroll
            for (int h = 0; h < 2; h++) {
                const int row = wm * 64 + mti * 16 + (lane >> 2) + h * 8;
                float sum = 0.f, sq = 0.f;
                #pragma unroll
                for (int j = 0; j < 4; j++) {
                    float4 v = *(float4*)&statb[row * 16 + j * 4];
                    sum += v.x + v.z;
                    sq  += v.y + v.w;
                }
                const float mu   = sum * (1.0f / 256.0f);
                const float var  = sq * (1.0f / 256.0f) - mu * mu;
                const float rstd = rsqrtf(var + LN_EPS);

                float* orow = out + (((size_t)(m0 + row) * 36 + p) * 256);
                #pragma unroll
                for (int ntl = 0; ntl < 4; ntl++) {
                    const int col = wn * 32 + ntl * 8 + (lane & 3) * 2;
                    float2 gvv = *(float2*)&gs[col];
                    float2 bvv = *(float2*)&bes[col];
                    float2 r;
                    r.x = (acc[mti][ntl][h * 2]     - mu) * rstd * gvv.x + bvv.x;
                    r.y = (acc[mti][ntl][h * 2 + 1] - mu) * rstd * gvv.y + bvv.y;
                    *(float2*)&orow[col] = r;
                }
            }
        __syncthreads();   // protect statb before next tile rewrites it
    }
}

// ===================== Launch =====================
extern "C" void kernel_launch(void* const* d_in, const int* in_sizes, int n_in,
                              void* d_out, int out_size) {
    const float* x_num = (const float*)d_in[0];
    const int*   x_cat = (const int*)d_in[1];
    const float* W1    = (const float*)d_in[2];
    const float* b1    = (const float*)d_in[3];
    const float* W2    = (const float*)d_in[4];
    const float* b2    = (const float*)d_in[5];
    const float* emb   = (const float*)d_in[6];
    const float* gamma = (const float*)d_in[7];
    const float* beta  = (const float*)d_in[8];
    float* out = (float*)d_out;

    cudaFuncSetAttribute(fused_kernel,
                         cudaFuncAttributeMaxDynamicSharedMemorySize, GEMM_SMEM);

    w2t_kernel<<<dim3(8, 8, 24), dim3(32, 8)>>>(W2);
    fused_kernel<<<GEMM_CTAS + CAT_CTAS, 512, GEMM_SMEM>>>(
        x_num, x_cat, W1, b1, b2, emb, gamma, beta, out);
}

// round 8
// speedup vs baseline: 1.5523x; 1.0529x over previous
#include <cuda_runtime.h>
#include <cuda_fp16.h>
#include <cstdint>

// ===================== Problem constants =====================
#define B_DIM 8192
#define P_DIM 24
#define Q_DIM 12
#define E_DIM 256
#define V_DIM 1000
#define LN_EPS 1e-5f

#define GEMM_CTAS 384          // 24 p * 16 m-slots (512 rows each, 256/half)
#define CAT_CTAS 192
#define TOK_PER_CAT_CTA 512    // 98304 / 192

// fp16 transposed W2: [p][f][e]  (K-major B operand), 3.1 MB static scratch
__device__ __half g_W2Th[P_DIM * E_DIM * E_DIM];

// ===================== Kernel 0: transpose + halve W2 =====================
__global__ void w2t_kernel(const float* __restrict__ W2) {
    __shared__ float tile[32][33];
    int p  = blockIdx.z;
    int e0 = blockIdx.y * 32;
    int f0 = blockIdx.x * 32;
    int tx = threadIdx.x, ty = threadIdx.y;
    #pragma unroll
    for (int i = ty; i < 32; i += 8)
        tile[i][tx] = W2[((size_t)p * 256 + e0 + i) * 256 + f0 + tx];
    __syncthreads();
    #pragma unroll
    for (int i = ty; i < 32; i += 8) {
        float v = tile[tx][i];
        g_W2Th[((size_t)p * 256 + f0 + i) * 256 + e0 + tx] = __float2half_rn(v);
    }
}

// ===================== Fused kernel: two independent 256-thread halves =====================
// SMEM byte offsets
#define SM_X    0        // 2 halves x 64 f = 512 B
#define SM_W1   1024     // 256 f
#define SM_B1   2048     // 256 f
#define SM_B2   3072     // 256 f
#define SM_G    4096     // 256 f
#define SM_BE   5120     // 256 f
#define SM_STAT 6144     // 2 halves x 64 rows x 16 f = 8192 B (ends 14336)
#define SM_A    16384    // 2 halves x 32768 B: A frags [ks(16)][mti(4)][lane(32)][4] b32
#define SM_B    81920    // 131072 B: B frags [ks(16)][ntp(16)][lane(32)][4] b32
#define GEMM_SMEM (81920 + 131072)   // 212992

#define HALF_BAR(id) asm volatile("bar.sync %0, %1;" :: "r"(id), "r"(256) : "memory")

__device__ __forceinline__ void mma16816(float* c, const uint32_t* a, const uint32_t* b) {
    asm volatile(
        "mma.sync.aligned.m16n8k16.row.col.f32.f16.f16.f32 "
        "{%0,%1,%2,%3}, {%4,%5,%6,%7}, {%8,%9}, {%0,%1,%2,%3};\n"
        : "+f"(c[0]), "+f"(c[1]), "+f"(c[2]), "+f"(c[3])
        : "r"(a[0]), "r"(a[1]), "r"(a[2]), "r"(a[3]), "r"(b[0]), "r"(b[1]));
}

__device__ __forceinline__ float gelu_exact(float t) {
    return 0.5f * t * (1.0f + erff(t * 0.70710678118654752f));
}

__global__ __launch_bounds__(512, 1)
void fused_kernel(const float* __restrict__ x_num,
                  const int*   __restrict__ x_cat,
                  const float* __restrict__ W1,
                  const float* __restrict__ b1,
                  const float* __restrict__ b2,
                  const float* __restrict__ emb,
                  const float* __restrict__ gamma,
                  const float* __restrict__ beta,
                  float* __restrict__ out) {
    const int tid  = threadIdx.x;
    const int lane = tid & 31;
    const int warp = tid >> 5;       // 0..15

    // ================= CAT PATH =================
    if (blockIdx.x >= GEMM_CTAS) {
        const int blk2 = blockIdx.x - GEMM_CTAS;
        const float4* g4  = (const float4*)gamma;
        const float4* be4 = (const float4*)beta;
        float4 g0 = g4[lane], g1 = g4[lane + 32];
        float4 e0 = be4[lane], e1 = be4[lane + 32];

        #pragma unroll 1
        for (int it = 0; it < TOK_PER_CAT_CTA / 16; it++) {
            const int tok = blk2 * TOK_PER_CAT_CTA + it * 16 + warp;
            const int b = tok / Q_DIM;
            const int q = tok % Q_DIM;
            const int idx = x_cat[(size_t)b * Q_DIM + q];
            const float4* src = (const float4*)(emb + ((size_t)q * V_DIM + idx) * E_DIM);
            float4 v0 = src[lane];
            float4 v1 = src[lane + 32];

            float sum = v0.x + v0.y + v0.z + v0.w + v1.x + v1.y + v1.z + v1.w;
            float sq  = v0.x * v0.x + v0.y * v0.y + v0.z * v0.z + v0.w * v0.w
                      + v1.x * v1.x + v1.y * v1.y + v1.z * v1.z + v1.w * v1.w;
            #pragma unroll
            for (int off = 16; off > 0; off >>= 1) {
                sum += __shfl_xor_sync(0xFFFFFFFFu, sum, off);
                sq  += __shfl_xor_sync(0xFFFFFFFFu, sq, off);
            }
            const float mu   = sum * (1.0f / 256.0f);
            const float var  = sq * (1.0f / 256.0f) - mu * mu;
            const float rstd = rsqrtf(var + LN_EPS);

            float4 r0, r1;
            r0.x = (v0.x - mu) * rstd * g0.x + e0.x;
            r0.y = (v0.y - mu) * rstd * g0.y + e0.y;
            r0.z = (v0.z - mu) * rstd * g0.z + e0.z;
            r0.w = (v0.w - mu) * rstd * g0.w + e0.w;
            r1.x = (v1.x - mu) * rstd * g1.x + e1.x;
            r1.y = (v1.y - mu) * rstd * g1.y + e1.y;
            r1.z = (v1.z - mu) * rstd * g1.z + e1.z;
            r1.w = (v1.w - mu) * rstd * g1.w + e1.w;

            float4* dst = (float4*)(out + ((size_t)b * 36 + 24 + q) * E_DIM);
            dst[lane] = r0;
            dst[lane + 32] = r1;
        }
        return;
    }

    // ================= GEMM PATH =================
    extern __shared__ char smem[];
    const int p     = blockIdx.x >> 4;   // 0..23
    const int mslot = blockIdx.x & 15;   // 0..15

    float* w1s = (float*)(smem + SM_W1);
    float* b1s = (float*)(smem + SM_B1);
    float* b2s = (float*)(smem + SM_B2);
    float* gs  = (float*)(smem + SM_G);
    float* bes = (float*)(smem + SM_BE);

    if (tid < 256) {
        w1s[tid] = W1[p * 256 + tid];
        b1s[tid] = b1[p * 256 + tid];
        b2s[tid] = b2[p * 256 + tid];
        gs[tid]  = gamma[tid];
        bes[tid] = beta[tid];
    }

    // ---- Stage B frags ONCE (read-only afterwards): warp = ks ----
    {
        const uint32_t* w2pu = (const uint32_t*)(g_W2Th + (size_t)p * 65536);
        uint4* bbuf4 = (uint4*)(smem + SM_B);
        const int ks = warp;
        const int ne_base = (lane >> 2);
        const int kh0 = ks * 8 + (lane & 3);
        const int kh1 = kh0 + 4;
        #pragma unroll
        for (int ntp = 0; ntp < 16; ntp++) {
            const int n_e = (2 * ntp) * 8 + ne_base;
            const int n_o = n_e + 8;
            uint4 v;
            v.x = w2pu[n_e * 128 + kh0];
            v.y = w2pu[n_e * 128 + kh1];
            v.z = w2pu[n_o * 128 + kh0];
            v.w = w2pu[n_o * 128 + kh1];
            bbuf4[(ks * 16 + ntp) * 32 + lane] = v;
        }
    }
    __syncthreads();   // B + consts visible to both halves; last block-wide barrier

    // ---- Half-CTA setup ----
    const int hh  = warp >> 3;          // half id 0/1
    const int wh  = warp & 7;           // warp within half (n octet, 32 cols)
    const int barid = 1 + hh;
    const int tidh = tid & 255;

    float* xs_h   = (float*)(smem + SM_X) + hh * 64;
    float* stat_h = (float*)(smem + SM_STAT) + hh * 1024;     // [64][16] floats
    char*  abuf_h = smem + SM_A + hh * 32768;

    float2 b2v[4];
    #pragma unroll
    for (int ntl = 0; ntl < 4; ntl++)
        b2v[ntl] = *(float2*)&b2s[wh * 32 + ntl * 8 + (lane & 3) * 2];

    const uint4* bfrag = (const uint4*)(smem + SM_B);
    const uint4* afrag = (const uint4*)abuf_h;

    // ---- Tile loop: 4 tiles of 64 rows per half ----
    for (int t = 0; t < 4; t++) {
        const int m0 = (mslot * 8 + hh * 4 + t) * 64;

        if (tidh < 64) xs_h[tidh] = x_num[(size_t)(m0 + tidh) * P_DIM + p];
        HALF_BAR(barid);

        // ---- Prologue: gelu(x*W1+b1) -> A frags; warp covers ks = wh, wh+8 ----
        #pragma unroll
        for (int kk = 0; kk < 2; kk++) {
            const int ks = wh + kk * 8;
            const int kbase = ks * 16 + (lane & 3) * 2;
            #pragma unroll
            for (int mti = 0; mti < 4; mti++) {
                const float xm0 = xs_h[mti * 16 + (lane >> 2)];
                const float xm1 = xs_h[mti * 16 + (lane >> 2) + 8];
                uint32_t r[4];
                #pragma unroll
                for (int reg = 0; reg < 4; reg++) {
                    const float xm = (reg & 1) ? xm1 : xm0;
                    const int k = kbase + (reg & 2) * 4;
                    float h0 = gelu_exact(xm * w1s[k]     + b1s[k]);
                    float h1 = gelu_exact(xm * w1s[k + 1] + b1s[k + 1]);
                    __half2 hv = __floats2half2_rn(h0, h1);
                    r[reg] = *reinterpret_cast<uint32_t*>(&hv);
                }
                *(uint4*)(abuf_h + ((ks * 4 + mti) * 32 + lane) * 16) =
                    make_uint4(r[0], r[1], r[2], r[3]);
            }
        }
        HALF_BAR(barid);

        // ---- Mainloop: warp tile 64 rows x 32 cols ----
        float acc[4][4][4];
        #pragma unroll
        for (int i = 0; i < 4; i++)
            #pragma unroll
            for (int j = 0; j < 4; j++)
                #pragma unroll
                for (int r = 0; r < 4; r++) acc[i][j][r] = 0.f;

        #pragma unroll
        for (int ks = 0; ks < 16; ks++) {
            uint32_t a[4][4];
            #pragma unroll
            for (int mti = 0; mti < 4; mti++) {
                uint4 v = afrag[(ks * 4 + mti) * 32 + lane];
                a[mti][0] = v.x; a[mti][1] = v.y; a[mti][2] = v.z; a[mti][3] = v.w;
            }
            #pragma unroll
            for (int i = 0; i < 2; i++) {
                uint4 bv4 = bfrag[(ks * 16 + wh * 2 + i) * 32 + lane];
                uint32_t b0[2] = {bv4.x, bv4.y};
                uint32_t b1r[2] = {bv4.z, bv4.w};
                #pragma unroll
                for (int mti = 0; mti < 4; mti++) {
                    mma16816(acc[mti][i * 2],     a[mti], b0);
                    mma16816(acc[mti][i * 2 + 1], a[mti], b1r);
                }
            }
        }

        // ---- Epilogue: +b2, LayerNorm ----
        #pragma unroll
        for (int mti = 0; mti < 4; mti++)
            #pragma unroll
            for (int ntl = 0; ntl < 4; ntl++) {
                acc[mti][ntl][0] += b2v[ntl].x;
                acc[mti][ntl][1] += b2v[ntl].y;
                acc[mti][ntl][2] += b2v[ntl].x;
                acc[mti][ntl][3] += b2v[ntl].y;
            }

        #pragma unroll
        for (int mti = 0; mti < 4; mti++)
            #pragma unroll
            for (int h = 0; h < 2; h++) {
                float s = 0.f, q = 0.f;
                #pragma unroll
                for (int ntl = 0; ntl < 4; ntl++) {
                    float v0 = acc[mti][ntl][h * 2];
                    float v1 = acc[mti][ntl][h * 2 + 1];
                    s += v0 + v1;
                    q += v0 * v0 + v1 * v1;
                }
                s += __shfl_xor_sync(0xFFFFFFFFu, s, 1);
                q += __shfl_xor_sync(0xFFFFFFFFu, q, 1);
                s += __shfl_xor_sync(0xFFFFFFFFu, s, 2);
                q += __shfl_xor_sync(0xFFFFFFFFu, q, 2);
                if ((lane & 3) == 0) {
                    const int row = mti * 16 + (lane >> 2) + h * 8;
                    *(float2*)&stat_h[row * 16 + wh * 2] = make_float2(s, q);
                }
            }
        HALF_BAR(barid);

        #pragma unroll
        for (int mti = 0; mti < 4; mti++)
            #pragma unroll
            for (int h = 0; h < 2; h++) {
                const int row = mti * 16 + (lane >> 2) + h * 8;
                float sum = 0.f, sq = 0.f;
                #pragma unroll
                for (int j = 0; j < 4; j++) {
                    float4 v = *(float4*)&stat_h[row * 16 + j * 4];
                    sum += v.x + v.z;
                    sq  += v.y + v.w;
                }
                const float mu   = sum * (1.0f / 256.0f);
                const float var  = sq * (1.0f / 256.0f) - mu * mu;
                const float rstd = rsqrtf(var + LN_EPS);

                float* orow = out + (((size_t)(m0 + row) * 36 + p) * 256);
                #pragma unroll
                for (int ntl = 0; ntl < 4; ntl++) {
                    const int col = wh * 32 + ntl * 8 + (lane & 3) * 2;
                    const float2 gvv = *(float2*)&gs[col];
                    const float2 bvv = *(float2*)&bes[col];
                    float2 r;
                    r.x = (acc[mti][ntl][h * 2]     - mu) * rstd * gvv.x + bvv.x;
                    r.y = (acc[mti][ntl][h * 2 + 1] - mu) * rstd * gvv.y + bvv.y;
                    *(float2*)&orow[col] = r;
                }
            }
        HALF_BAR(barid);   // protect xs_h / abuf_h / stat_h before next tile
    }
}

// ===================== Launch =====================
extern "C" void kernel_launch(void* const* d_in, const int* in_sizes, int n_in,
                              void* d_out, int out_size) {
    const float* x_num = (const float*)d_in[0];
    const int*   x_cat = (const int*)d_in[1];
    const float* W1    = (const float*)d_in[2];
    const float* b1    = (const float*)d_in[3];
    const float* W2    = (const float*)d_in[4];
    const float* b2    = (const float*)d_in[5];
    const float* emb   = (const float*)d_in[6];
    const float* gamma = (const float*)d_in[7];
    const float* beta  = (const float*)d_in[8];
    float* out = (float*)d_out;

    cudaFuncSetAttribute(fused_kernel,
                         cudaFuncAttributeMaxDynamicSharedMemorySize, GEMM_SMEM);

    w2t_kernel<<<dim3(8, 8, 24), dim3(32, 8)>>>(W2);
    fused_kernel<<<GEMM_CTAS + CAT_CTAS, 512, GEMM_SMEM>>>(
        x_num, x_cat, W1, b1, b2, emb, gamma, beta, out);
}